// round 2
// baseline (speedup 1.0000x reference)
#include <cuda_runtime.h>

#define NB 2
#define NN 2048
#define FIN 128
#define FE 64
#define BN2 (NB*NN*NN)                 // 8388608
#define OFF_ROWS 262144
#define OFF_WGT  (262144 + 2*BN2)      // 17039360

__device__ float g_xw[NB*NN*FE];       // x @ W
__device__ float g_part[2*NB*NN*FE];   // k-split partials of A@xw
__device__ float g_cent[NB*FE];
__device__ float g_usq[NB*NN];         // unscaled sum((x-c)^2) per row
__device__ unsigned int g_maxbits;     // max |x-c| as float bits

// ---------------- K0: xw = x @ W  (tiny GEMM, W resident in smem) ------------
__global__ void k0_xw(const float* __restrict__ x, const float* __restrict__ W) {
    __shared__ float Wsh[FIN*FE];      // 32 KB
    __shared__ float xsh[4][FIN];
    int tid = threadIdx.x;             // 256
    for (int i = tid; i < FIN*FE; i += 256) Wsh[i] = W[i];
    int rowBase = blockIdx.x * 16;
    int rloc = tid >> 6, e = tid & 63;
    for (int pass = 0; pass < 4; ++pass) {
        __syncthreads();
        int r0 = rowBase + pass * 4;
        for (int i = tid; i < 4*FIN; i += 256)
            xsh[i >> 7][i & 127] = x[(size_t)r0*FIN + i];
        __syncthreads();
        float acc = 0.f;
        #pragma unroll
        for (int k = 0; k < FIN; ++k)
            acc = fmaf(xsh[rloc][k], Wsh[k*FE + e], acc);
        g_xw[(size_t)(r0 + rloc)*FE + e] = acc;
    }
}

// ---------------- K1: partial = A @ xw  (BM=64, BN=64, BK=32, ksplit=2) ------
__global__ void k1_gemm(const float* __restrict__ A) {
    __shared__ float Ast[32][68];      // [k][row], transposed for LDS.128
    __shared__ float Xs[32][68];       // [k][e]
    int b = blockIdx.z, ks = blockIdx.y;
    int i0 = blockIdx.x * 64;
    int tid = threadIdx.x;
    int ty = tid >> 4, tx = tid & 15;
    const float* Ab = A + (size_t)b*NN*NN;
    const float* Xb = g_xw + (size_t)b*NN*FE;
    float acc[4][4] = {};
    int kbeg = ks * (NN/2), kend = kbeg + NN/2;
    for (int k0 = kbeg; k0 < kend; k0 += 32) {
        {   // A tile 64 rows x 32 k -> transposed
            int r = tid >> 2;
            int kq = (tid & 3) * 4;
            #pragma unroll
            for (int half = 0; half < 2; ++half) {
                int kk = kq + half*16;
                float4 v = *(const float4*)(Ab + (size_t)(i0 + r)*NN + k0 + kk);
                Ast[kk+0][r] = v.x; Ast[kk+1][r] = v.y;
                Ast[kk+2][r] = v.z; Ast[kk+3][r] = v.w;
            }
        }
        {   // X tile 32 k x 64 e
            int kk = tid >> 4;
            int e4 = (tid & 15) * 4;
            #pragma unroll
            for (int half = 0; half < 2; ++half) {
                int kr = kk + half*16;
                float4 v = *(const float4*)(Xb + (size_t)(k0 + kr)*FE + e4);
                Xs[kr][e4+0] = v.x; Xs[kr][e4+1] = v.y;
                Xs[kr][e4+2] = v.z; Xs[kr][e4+3] = v.w;
            }
        }
        __syncthreads();
        #pragma unroll
        for (int kk = 0; kk < 32; ++kk) {
            float4 a = *(const float4*)&Ast[kk][ty*4];
            float4 x4 = *(const float4*)&Xs[kk][tx*4];
            acc[0][0] = fmaf(a.x, x4.x, acc[0][0]);
            acc[0][1] = fmaf(a.x, x4.y, acc[0][1]);
            acc[0][2] = fmaf(a.x, x4.z, acc[0][2]);
            acc[0][3] = fmaf(a.x, x4.w, acc[0][3]);
            acc[1][0] = fmaf(a.y, x4.x, acc[1][0]);
            acc[1][1] = fmaf(a.y, x4.y, acc[1][1]);
            acc[1][2] = fmaf(a.y, x4.z, acc[1][2]);
            acc[1][3] = fmaf(a.y, x4.w, acc[1][3]);
            acc[2][0] = fmaf(a.z, x4.x, acc[2][0]);
            acc[2][1] = fmaf(a.z, x4.y, acc[2][1]);
            acc[2][2] = fmaf(a.z, x4.z, acc[2][2]);
            acc[2][3] = fmaf(a.z, x4.w, acc[2][3]);
            acc[3][0] = fmaf(a.w, x4.x, acc[3][0]);
            acc[3][1] = fmaf(a.w, x4.y, acc[3][1]);
            acc[3][2] = fmaf(a.w, x4.z, acc[3][2]);
            acc[3][3] = fmaf(a.w, x4.w, acc[3][3]);
        }
        __syncthreads();
    }
    float* P = g_part + (size_t)ks*NB*NN*FE + (size_t)b*NN*FE;
    #pragma unroll
    for (int i = 0; i < 4; ++i) {
        float4 v = make_float4(acc[i][0], acc[i][1], acc[i][2], acc[i][3]);
        *(float4*)(P + (size_t)(i0 + ty*4 + i)*FE + tx*4) = v;
    }
}

// ---------------- K1b: x_emb = relu(partial0 + partial1 + bias) --------------
__global__ void k1b_bias(const float* __restrict__ bias, float* __restrict__ out) {
    int i = blockIdx.x*blockDim.x + threadIdx.x;     // exactly 262144 threads
    float v = g_part[i] + g_part[NB*NN*FE + i] + bias[i & 63];
    out[i] = fmaxf(v, 0.f);
}

// ---------------- K2: centroid = mean over N (per batch, per e) --------------
__global__ void k2_cent(const float* __restrict__ xemb) {
    int be = blockIdx.x;               // 0..127
    int b = be >> 6, e = be & 63;
    const float* p = xemb + (size_t)b*NN*FE + e;
    float s = 0.f;
    for (int n = threadIdx.x; n < NN; n += 256)
        s += p[(size_t)n*FE];
    __shared__ float sm[256];
    sm[threadIdx.x] = s; __syncthreads();
    for (int st = 128; st; st >>= 1) {
        if (threadIdx.x < st) sm[threadIdx.x] += sm[threadIdx.x + st];
        __syncthreads();
    }
    if (threadIdx.x == 0) g_cent[be] = sm[0] * (1.f/NN);
    if (be == 0 && threadIdx.x == 0) g_maxbits = 0u;
}

// ---------------- K3: per-row usq + global max|x-c| --------------------------
__global__ void k3_usq(const float* __restrict__ xemb) {
    int bid = blockIdx.x;              // 0..4095 (b*N + n)
    int b = bid >> 11;
    int e = threadIdx.x;               // 0..63
    float v = xemb[(size_t)bid*FE + e] - g_cent[b*FE + e];
    float sq = v*v, av = fabsf(v);
    #pragma unroll
    for (int o = 16; o; o >>= 1) {
        sq += __shfl_down_sync(0xffffffffu, sq, o);
        av = fmaxf(av, __shfl_down_sync(0xffffffffu, av, o));
    }
    __shared__ float s0[2], s1[2];
    if ((e & 31) == 0) { s0[e>>5] = sq; s1[e>>5] = av; }
    __syncthreads();
    if (e == 0) {
        g_usq[bid] = s0[0] + s0[1];
        atomicMax(&g_maxbits, __float_as_uint(fmaxf(s1[0], s1[1])));
    }
}

// ---------------- K4: edge_index (pure index function), float4 stores --------
__global__ void k4_idx(float* __restrict__ out) {
    long long t = (long long)blockIdx.x*blockDim.x + threadIdx.x;
    const long long total4 = (2LL*BN2) >> 2;
    float4* dst = (float4*)(out + OFF_ROWS);
    long long stride = (long long)gridDim.x * blockDim.x;
    for (; t < total4; t += stride) {
        long long k = t << 2;
        float4 v;
        if (k < BN2) {
            float r = (float)(k >> 11);              // idx // N
            v = make_float4(r, r, r, r);
        } else {
            long long j = k - BN2;
            float base = (float)((j & 2047) + ((j >> 22) << 11));  // col + N*batch
            v = make_float4(base, base+1.f, base+2.f, base+3.f);
        }
        dst[t] = v;
    }
}

// ---------------- K5: Gram + distances + sigmoid weights ---------------------
__global__ void k5_gram(const float* __restrict__ xemb,
                        const float* __restrict__ temp, const float* __restrict__ thr,
                        float* __restrict__ out) {
    __shared__ float Tit[64][68];      // [e][row_i], centered (unscaled)
    __shared__ float Tjt[64][68];      // [e][row_j]
    __shared__ float usqi[64], usqj[64];
    int b = blockIdx.z;
    int i0 = blockIdx.y * 64, j0 = blockIdx.x * 64;
    int tid = threadIdx.x;
    const float* Xb = xemb + (size_t)b*NN*FE;
    {
        int r = tid >> 2;              // 0..63
        int eq = (tid & 3) * 4;
        #pragma unroll
        for (int h = 0; h < 4; ++h) {
            int e = eq + h*16;
            float4 ci = *(const float4*)(&g_cent[b*FE + e]);
            float4 v = *(const float4*)(Xb + (size_t)(i0 + r)*FE + e);
            Tit[e+0][r] = v.x - ci.x; Tit[e+1][r] = v.y - ci.y;
            Tit[e+2][r] = v.z - ci.z; Tit[e+3][r] = v.w - ci.w;
            float4 w = *(const float4*)(Xb + (size_t)(j0 + r)*FE + e);
            Tjt[e+0][r] = w.x - ci.x; Tjt[e+1][r] = w.y - ci.y;
            Tjt[e+2][r] = w.z - ci.z; Tjt[e+3][r] = w.w - ci.w;
        }
    }
    if (tid < 64)       usqi[tid]     = g_usq[b*NN + i0 + tid];
    else if (tid < 128) usqj[tid-64]  = g_usq[b*NN + j0 + (tid-64)];
    __syncthreads();

    int ty = tid >> 4, tx = tid & 15;
    float acc[4][4] = {};
    #pragma unroll
    for (int k = 0; k < 64; ++k) {
        float4 a  = *(const float4*)&Tit[k][ty*4];
        float4 x4 = *(const float4*)&Tjt[k][tx*4];
        acc[0][0] = fmaf(a.x, x4.x, acc[0][0]);
        acc[0][1] = fmaf(a.x, x4.y, acc[0][1]);
        acc[0][2] = fmaf(a.x, x4.z, acc[0][2]);
        acc[0][3] = fmaf(a.x, x4.w, acc[0][3]);
        acc[1][0] = fmaf(a.y, x4.x, acc[1][0]);
        acc[1][1] = fmaf(a.y, x4.y, acc[1][1]);
        acc[1][2] = fmaf(a.y, x4.z, acc[1][2]);
        acc[1][3] = fmaf(a.y, x4.w, acc[1][3]);
        acc[2][0] = fmaf(a.z, x4.x, acc[2][0]);
        acc[2][1] = fmaf(a.z, x4.y, acc[2][1]);
        acc[2][2] = fmaf(a.z, x4.z, acc[2][2]);
        acc[2][3] = fmaf(a.z, x4.w, acc[2][3]);
        acc[3][0] = fmaf(a.w, x4.x, acc[3][0]);
        acc[3][1] = fmaf(a.w, x4.y, acc[3][1]);
        acc[3][2] = fmaf(a.w, x4.z, acc[3][2]);
        acc[3][3] = fmaf(a.w, x4.w, acc[3][3]);
    }
    float mx = __uint_as_float(g_maxbits);
    float s = 0.9f / mx, s2 = s * s;
    float T = *temp, TH = fabsf(*thr);
    float* Ob = out + OFF_WGT + (size_t)b*NN*NN;
    #pragma unroll
    for (int i = 0; i < 4; ++i) {
        float ui = usqi[ty*4 + i];
        float w[4];
        #pragma unroll
        for (int j = 0; j < 4; ++j) {
            float d = s2 * (ui + usqj[tx*4 + j] - 2.f*acc[i][j]);
            d = fmaxf(d, 0.f);
            float z = T * (TH - d);
            w[j] = __fdividef(1.f, 1.f + __expf(-z));
        }
        float4 v = make_float4(w[0], w[1], w[2], w[3]);
        *(float4*)(Ob + (size_t)(i0 + ty*4 + i)*NN + j0 + tx*4) = v;
    }
}

extern "C" void kernel_launch(void* const* d_in, const int* in_sizes, int n_in,
                              void* d_out, int out_size) {
    const float* x    = (const float*)d_in[0];
    const float* A    = (const float*)d_in[1];
    const float* W    = (const float*)d_in[2];
    const float* bias = (const float*)d_in[3];
    const float* temp = (const float*)d_in[4];
    const float* thr  = (const float*)d_in[5];
    float* out = (float*)d_out;

    k0_xw<<<NB*NN/16, 256>>>(x, W);
    k1_gemm<<<dim3(NN/64, 2, NB), 256>>>(A);
    k1b_bias<<<(NB*NN*FE)/256, 256>>>(bias, out);
    k2_cent<<<NB*FE, 256>>>(out);
    k3_usq<<<NB*NN, 64>>>(out);
    k4_idx<<<4096, 256>>>(out);
    k5_gram<<<dim3(NN/64, NN/64, NB), 256>>>(out, temp, thr, out);
}

// round 3
// speedup vs baseline: 1.1850x; 1.1850x over previous
#include <cuda_runtime.h>

#define NB 2
#define NN 2048
#define FIN 128
#define FE 64
#define BN2 (NB*NN*NN)                 // 8388608
#define OFF_ROWS 262144
#define OFF_WGT  (262144 + 2*BN2)      // 17039360
#define KS 8                           // k-split for K1
#define SLICE (NB*NN*FE)               // 262144

__device__ float g_xw[NB*NN*FE];       // x @ W
__device__ float g_part[KS*NB*NN*FE];  // k-split partials of A@xw
__device__ float g_cent[NB*FE];
__device__ float g_usq[NB*NN];         // unscaled sum((x-c)^2) per row
__device__ unsigned int g_maxbits;     // max |x-c| as float bits

// packed fp32x2 FMA (Blackwell): d = a*b + c elementwise on float pairs
__device__ __forceinline__ unsigned long long fma2(unsigned long long a,
                                                   unsigned long long b,
                                                   unsigned long long c) {
    unsigned long long d;
    asm("fma.rn.f32x2 %0, %1, %2, %3;" : "=l"(d) : "l"(a), "l"(b), "l"(c));
    return d;
}
__device__ __forceinline__ float fsum2(unsigned long long v) {
    float2 f = *reinterpret_cast<float2*>(&v);
    return f.x + f.y;
}

// ---------------- K0: xw = x @ W  (tiny GEMM, W resident in smem) ------------
__global__ void k0_xw(const float* __restrict__ x, const float* __restrict__ W) {
    __shared__ float Wsh[FIN*FE];      // 32 KB
    __shared__ float xsh[4][FIN];
    int tid = threadIdx.x;             // 256
    if (blockIdx.x == 0) {             // zero accumulators for later kernels
        if (tid < NB*FE) g_cent[tid] = 0.f;
        if (tid == 128) g_maxbits = 0u;
    }
    for (int i = tid; i < FIN*FE; i += 256) Wsh[i] = W[i];
    int rowBase = blockIdx.x * 16;
    int rloc = tid >> 6, e = tid & 63;
    for (int pass = 0; pass < 4; ++pass) {
        __syncthreads();
        int r0 = rowBase + pass * 4;
        for (int i = tid; i < 4*FIN; i += 256)
            xsh[i >> 7][i & 127] = x[(size_t)r0*FIN + i];
        __syncthreads();
        float acc = 0.f;
        #pragma unroll
        for (int k = 0; k < FIN; ++k)
            acc = fmaf(xsh[rloc][k], Wsh[k*FE + e], acc);
        g_xw[(size_t)(r0 + rloc)*FE + e] = acc;
    }
}

// ---------------- K1: partial = A @ xw  (BM=128, BN=64, BK=32, ksplit=8) -----
// k-contiguous swizzled tiles, 8x8 microtile, fp32x2 FMA paired along K.
__global__ void __launch_bounds__(128) k1_gemm(const float* __restrict__ A) {
    __shared__ float As[128][32];      // As[row][k^sw(row)] 16KB
    __shared__ float Xs[64][32];       // Xs[e][k^sw(e)]     8KB
    int b = blockIdx.z, ks = blockIdx.y;
    int i0 = blockIdx.x * 128;
    int tid = threadIdx.x;
    const float* Ab = A + (size_t)b*NN*NN;
    const float* Xb = g_xw + (size_t)b*NN*FE;
    int ri = (tid >> 3) * 8;           // 0..120
    int ej = (tid & 7) * 8;            // 0..56
    int swa = ((tid >> 3) & 7) * 4;
    int swb = (tid & 7) * 4;
    unsigned long long acc[8][8];
    #pragma unroll
    for (int i = 0; i < 8; ++i)
        #pragma unroll
        for (int j = 0; j < 8; ++j) acc[i][j] = 0ull;

    int kbeg = ks * (NN/KS);
    for (int k0 = kbeg; k0 < kbeg + NN/KS; k0 += 32) {
        #pragma unroll
        for (int v = 0; v < 8; ++v) {          // A tile: 128 rows x 32 k
            int idx = tid + v*128;
            int row = idx >> 3, kq = (idx & 7) * 4;
            float4 t = *(const float4*)(Ab + (size_t)(i0 + row)*NN + k0 + kq);
            *(float4*)&As[row][kq ^ (((row >> 3) & 7) * 4)] = t;
        }
        #pragma unroll
        for (int v = 0; v < 4; ++v) {          // X tile: 32 k x 64 e -> [e][k]
            int idx = tid + v*128;
            int kk = idx >> 4, e4 = (idx & 15) * 4;
            float4 t = *(const float4*)(Xb + (size_t)(k0 + kk)*FE + e4);
            int sw = ((e4 >> 3) & 7) * 4;
            Xs[e4+0][kk ^ sw] = t.x; Xs[e4+1][kk ^ sw] = t.y;
            Xs[e4+2][kk ^ sw] = t.z; Xs[e4+3][kk ^ sw] = t.w;
        }
        __syncthreads();
        #pragma unroll
        for (int kk = 0; kk < 32; kk += 4) {
            ulonglong2 a2[8], b2[8];
            #pragma unroll
            for (int i = 0; i < 8; ++i)
                a2[i] = *(const ulonglong2*)&As[ri + i][kk ^ swa];
            #pragma unroll
            for (int j = 0; j < 8; ++j)
                b2[j] = *(const ulonglong2*)&Xs[ej + j][kk ^ swb];
            #pragma unroll
            for (int i = 0; i < 8; ++i)
                #pragma unroll
                for (int j = 0; j < 8; ++j) {
                    acc[i][j] = fma2(a2[i].x, b2[j].x, acc[i][j]);
                    acc[i][j] = fma2(a2[i].y, b2[j].y, acc[i][j]);
                }
        }
        __syncthreads();
    }
    float* P = g_part + (size_t)ks*SLICE + (size_t)b*NN*FE;
    #pragma unroll
    for (int i = 0; i < 8; ++i) {
        float4 v0 = make_float4(fsum2(acc[i][0]), fsum2(acc[i][1]),
                                fsum2(acc[i][2]), fsum2(acc[i][3]));
        float4 v1 = make_float4(fsum2(acc[i][4]), fsum2(acc[i][5]),
                                fsum2(acc[i][6]), fsum2(acc[i][7]));
        float* p = P + (size_t)(i0 + ri + i)*FE + ej;
        *(float4*)p       = v0;
        *(float4*)(p + 4) = v1;
    }
}

// ---------------- K1b: x_emb = relu(sum partials + bias), + centroid sums ----
__global__ void k1b_bias(const float* __restrict__ bias, float* __restrict__ out) {
    int tid = threadIdx.x;                     // 1024
    int i = blockIdx.x * 1024 + tid;           // 256 blocks cover 262144
    float v = bias[i & 63];
    #pragma unroll
    for (int s = 0; s < KS; ++s) v += g_part[(size_t)s*SLICE + i];
    v = fmaxf(v, 0.f);
    out[i] = v;
    __shared__ float cs[64];
    if (tid < 64) cs[tid] = 0.f;
    __syncthreads();
    atomicAdd(&cs[tid & 63], v);
    __syncthreads();
    if (tid < 64) {
        int b = blockIdx.x >> 7;               // 16 rows per block, 128 blocks/batch
        atomicAdd(&g_cent[b*FE + tid], cs[tid] * (1.f/NN));
    }
}

// ---------------- K3: per-row usq + global max|x-c| --------------------------
__global__ void k3_usq(const float* __restrict__ xemb) {
    int bid = blockIdx.x;              // 0..4095 (b*N + n)
    int b = bid >> 11;
    int e = threadIdx.x;               // 0..63
    float v = xemb[(size_t)bid*FE + e] - g_cent[b*FE + e];
    float sq = v*v, av = fabsf(v);
    #pragma unroll
    for (int o = 16; o; o >>= 1) {
        sq += __shfl_down_sync(0xffffffffu, sq, o);
        av = fmaxf(av, __shfl_down_sync(0xffffffffu, av, o));
    }
    __shared__ float s0[2], s1[2];
    if ((e & 31) == 0) { s0[e>>5] = sq; s1[e>>5] = av; }
    __syncthreads();
    if (e == 0) {
        g_usq[bid] = s0[0] + s0[1];
        atomicMax(&g_maxbits, __float_as_uint(fmaxf(s1[0], s1[1])));
    }
}

// ---------------- K4: edge_index (pure index function), float4 stores --------
__global__ void k4_idx(float* __restrict__ out) {
    long long t = (long long)blockIdx.x*blockDim.x + threadIdx.x;
    const long long total4 = (2LL*BN2) >> 2;
    float4* dst = (float4*)(out + OFF_ROWS);
    long long stride = (long long)gridDim.x * blockDim.x;
    for (; t < total4; t += stride) {
        long long k = t << 2;
        float4 v;
        if (k < BN2) {
            float r = (float)(k >> 11);              // idx // N
            v = make_float4(r, r, r, r);
        } else {
            long long j = k - BN2;
            float base = (float)((j & 2047) + ((j >> 22) << 11));  // col + N*batch
            v = make_float4(base, base+1.f, base+2.f, base+3.f);
        }
        dst[t] = v;
    }
}

// ---------------- K5: Gram + distances + sigmoid weights ---------------------
// BM=128(i) x BN=64(j), K=64, 8x8 microtile, fp32x2 paired along K.
__global__ void __launch_bounds__(128) k5_gram(const float* __restrict__ xemb,
                        const float* __restrict__ temp, const float* __restrict__ thr,
                        float* __restrict__ out) {
    __shared__ float Ti[128][64];      // [i][e^sw] centered, 32KB
    __shared__ float Tj[64][64];       // [j][e^sw] centered, 16KB
    __shared__ float usqi[128], usqj[64];
    int b = blockIdx.z;
    int i0 = blockIdx.y * 128, j0 = blockIdx.x * 64;
    int tid = threadIdx.x;
    const float* Xb = xemb + (size_t)b*NN*FE;
    #pragma unroll
    for (int v = 0; v < 16; ++v) {     // Ti fill: 128 rows x 64 e
        int idx = tid + v*128;
        int row = idx >> 4, e4 = (idx & 15) * 4;
        float4 c = *(const float4*)&g_cent[b*FE + e4];
        float4 t = *(const float4*)(Xb + (size_t)(i0 + row)*FE + e4);
        t.x -= c.x; t.y -= c.y; t.z -= c.z; t.w -= c.w;
        *(float4*)&Ti[row][e4 ^ (((row >> 3) & 7) * 4)] = t;
    }
    #pragma unroll
    for (int v = 0; v < 8; ++v) {      // Tj fill: 64 rows x 64 e
        int idx = tid + v*128;
        int row = idx >> 4, e4 = (idx & 15) * 4;
        float4 c = *(const float4*)&g_cent[b*FE + e4];
        float4 t = *(const float4*)(Xb + (size_t)(j0 + row)*FE + e4);
        t.x -= c.x; t.y -= c.y; t.z -= c.z; t.w -= c.w;
        *(float4*)&Tj[row][e4 ^ (((row >> 3) & 7) * 4)] = t;
    }
    usqi[tid] = g_usq[b*NN + i0 + tid];
    if (tid < 64) usqj[tid] = g_usq[b*NN + j0 + tid];
    __syncthreads();

    int ri = (tid >> 3) * 8;
    int ej = (tid & 7) * 8;
    int swa = ((tid >> 3) & 7) * 4;
    int swb = (tid & 7) * 4;
    unsigned long long acc[8][8];
    #pragma unroll
    for (int i = 0; i < 8; ++i)
        #pragma unroll
        for (int j = 0; j < 8; ++j) acc[i][j] = 0ull;

    #pragma unroll
    for (int kk = 0; kk < 64; kk += 4) {
        ulonglong2 a2[8], b2[8];
        #pragma unroll
        for (int i = 0; i < 8; ++i)
            a2[i] = *(const ulonglong2*)&Ti[ri + i][kk ^ swa];
        #pragma unroll
        for (int j = 0; j < 8; ++j)
            b2[j] = *(const ulonglong2*)&Tj[ej + j][kk ^ swb];
        #pragma unroll
        for (int i = 0; i < 8; ++i)
            #pragma unroll
            for (int j = 0; j < 8; ++j) {
                acc[i][j] = fma2(a2[i].x, b2[j].x, acc[i][j]);
                acc[i][j] = fma2(a2[i].y, b2[j].y, acc[i][j]);
            }
    }

    float mx = __uint_as_float(g_maxbits);
    float s = 0.9f / mx, s2 = s * s;
    float T = *temp, TH = fabsf(*thr);
    float* Ob = out + OFF_WGT + (size_t)b*NN*NN;
    #pragma unroll
    for (int i = 0; i < 8; ++i) {
        float ui = usqi[ri + i];
        float w[8];
        #pragma unroll
        for (int j = 0; j < 8; ++j) {
            float d = s2 * (ui + usqj[ej + j] - 2.f * fsum2(acc[i][j]));
            d = fmaxf(d, 0.f);
            float z = T * (TH - d);
            w[j] = __fdividef(1.f, 1.f + __expf(-z));
        }
        float* p = Ob + (size_t)(i0 + ri + i)*NN + j0 + ej;
        *(float4*)p       = make_float4(w[0], w[1], w[2], w[3]);
        *(float4*)(p + 4) = make_float4(w[4], w[5], w[6], w[7]);
    }
}

extern "C" void kernel_launch(void* const* d_in, const int* in_sizes, int n_in,
                              void* d_out, int out_size) {
    const float* x    = (const float*)d_in[0];
    const float* A    = (const float*)d_in[1];
    const float* W    = (const float*)d_in[2];
    const float* bias = (const float*)d_in[3];
    const float* temp = (const float*)d_in[4];
    const float* thr  = (const float*)d_in[5];
    float* out = (float*)d_out;

    k0_xw<<<NB*NN/16, 256>>>(x, W);
    k1_gemm<<<dim3(NN/128, KS, NB), 128>>>(A);
    k1b_bias<<<(NB*NN*FE)/1024, 1024>>>(bias, out);
    k3_usq<<<NB*NN, 64>>>(out);
    k4_idx<<<4096, 256>>>(out);
    k5_gram<<<dim3(NN/64, NN/128, NB), 128>>>(out, temp, thr, out);
}

// round 4
// speedup vs baseline: 1.2500x; 1.0548x over previous
#include <cuda_runtime.h>

#define NB 2
#define NN 2048
#define FIN 128
#define FE 64
#define BN2 (NB*NN*NN)                 // 8388608
#define OFF_ROWS 262144
#define OFF_WGT  (262144 + 2*BN2)      // 17039360
#define KS 8                           // k-split for K1
#define SLICE (NB*NN*FE)               // 262144

typedef unsigned long long ull;

__device__ float g_xw[NB*NN*FE];       // x @ W
__device__ float g_part[KS*NB*NN*FE];  // k-split partials of A@xw
__device__ float g_cent[NB*FE];
__device__ float g_usq[NB*NN];         // unscaled sum((x-c)^2) per row
__device__ unsigned int g_maxbits;     // max |x-c| as float bits

// packed fp32x2 FMA (Blackwell): d = a*b + c elementwise on float pairs
__device__ __forceinline__ ull fma2(ull a, ull b, ull c) {
    ull d;
    asm("fma.rn.f32x2 %0, %1, %2, %3;" : "=l"(d) : "l"(a), "l"(b), "l"(c));
    return d;
}
__device__ __forceinline__ float fsum2(ull v) {
    float2 f = *reinterpret_cast<float2*>(&v);
    return f.x + f.y;
}
// row-dependent swizzle of the k-contiguous column index (keeps 8B alignment)
__device__ __forceinline__ int swz(int r) { return ((r >> 2) & 15) * 2; }

// ---------------- K0: xw = x @ W  (tiny GEMM, W resident in smem) ------------
__global__ void k0_xw(const float* __restrict__ x, const float* __restrict__ W) {
    __shared__ float Wsh[FIN*FE];      // 32 KB
    __shared__ float xsh[4][FIN];
    int tid = threadIdx.x;             // 256
    if (blockIdx.x == 0) {             // zero accumulators for later kernels
        if (tid < NB*FE) g_cent[tid] = 0.f;
        if (tid == 128) g_maxbits = 0u;
    }
    for (int i = tid; i < FIN*FE; i += 256) Wsh[i] = W[i];
    int rowBase = blockIdx.x * 16;
    int rloc = tid >> 6, e = tid & 63;
    for (int pass = 0; pass < 4; ++pass) {
        __syncthreads();
        int r0 = rowBase + pass * 4;
        for (int i = tid; i < 4*FIN; i += 256)
            xsh[i >> 7][i & 127] = x[(size_t)r0*FIN + i];
        __syncthreads();
        float acc = 0.f;
        #pragma unroll
        for (int k = 0; k < FIN; ++k)
            acc = fmaf(xsh[rloc][k], Wsh[k*FE + e], acc);
        g_xw[(size_t)(r0 + rloc)*FE + e] = acc;
    }
}

// ---------------- K1: partial = A @ xw  (BM=128, BN=64, BK=32, ksplit=8) -----
// 256 threads, 8x4 fma2 microtile, swizzled k-contiguous tiles, LDS.64 operands.
__global__ void __launch_bounds__(256) k1_gemm(const float* __restrict__ A) {
    __shared__ float As[128][32];      // [row][k^swz(row)] 16KB
    __shared__ float Xs[64][32];       // [e][k^swz(e)]     8KB
    int b = blockIdx.z, ks = blockIdx.y;
    int i0 = blockIdx.x * 128;
    int tid = threadIdx.x;
    int ty = tid >> 4, tx = tid & 15;
    int ri = ty * 8, ej = tx * 4;
    int fA = ((2*ty) & 15) * 2, fB = ((2*ty + 1) & 15) * 2, fb = 2 * tx;
    const float* Ab = A + (size_t)b*NN*NN;
    const float* Xb = g_xw + (size_t)b*NN*FE;
    ull acc[8][4];
    #pragma unroll
    for (int i = 0; i < 8; ++i)
        #pragma unroll
        for (int j = 0; j < 4; ++j) acc[i][j] = 0ull;

    int kbeg = ks * (NN/KS);
    for (int k0 = kbeg; k0 < kbeg + NN/KS; k0 += 32) {
        #pragma unroll
        for (int v = 0; v < 4; ++v) {          // A tile: 128 rows x 32 k
            int idx = tid + v*256;
            int row = idx >> 3, kq = (idx & 7) * 4;
            float4 t = *(const float4*)(Ab + (size_t)(i0 + row)*NN + k0 + kq);
            int f = swz(row);
            *(float2*)&As[row][(kq    ) ^ f] = make_float2(t.x, t.y);
            *(float2*)&As[row][(kq + 2) ^ f] = make_float2(t.z, t.w);
        }
        #pragma unroll
        for (int v = 0; v < 2; ++v) {          // X tile: 32 k x 64 e -> [e][k]
            int idx = tid + v*256;
            int kk = idx >> 4, e4 = (idx & 15) * 4;
            float4 t = *(const float4*)(Xb + (size_t)(k0 + kk)*FE + e4);
            Xs[e4+0][kk ^ swz(e4+0)] = t.x;
            Xs[e4+1][kk ^ swz(e4+1)] = t.y;
            Xs[e4+2][kk ^ swz(e4+2)] = t.z;
            Xs[e4+3][kk ^ swz(e4+3)] = t.w;
        }
        __syncthreads();
        #pragma unroll
        for (int kk = 0; kk < 32; kk += 2) {
            ull a2[8], b2[4];
            #pragma unroll
            for (int i = 0; i < 8; ++i)
                a2[i] = *(const ull*)&As[ri + i][kk ^ (i < 4 ? fA : fB)];
            #pragma unroll
            for (int j = 0; j < 4; ++j)
                b2[j] = *(const ull*)&Xs[ej + j][kk ^ fb];
            #pragma unroll
            for (int i = 0; i < 8; ++i)
                #pragma unroll
                for (int j = 0; j < 4; ++j)
                    acc[i][j] = fma2(a2[i], b2[j], acc[i][j]);
        }
        __syncthreads();
    }
    float* P = g_part + (size_t)ks*SLICE + (size_t)b*NN*FE;
    #pragma unroll
    for (int i = 0; i < 8; ++i) {
        float4 v = make_float4(fsum2(acc[i][0]), fsum2(acc[i][1]),
                               fsum2(acc[i][2]), fsum2(acc[i][3]));
        *(float4*)(P + (size_t)(i0 + ri + i)*FE + ej) = v;
    }
}

// ---------------- K1b: x_emb = relu(sum partials + bias), + centroid sums ----
__global__ void k1b_bias(const float* __restrict__ bias, float* __restrict__ out) {
    int tid = threadIdx.x;                     // 1024
    int i = blockIdx.x * 1024 + tid;           // 256 blocks cover 262144
    float v = bias[i & 63];
    #pragma unroll
    for (int s = 0; s < KS; ++s) v += g_part[(size_t)s*SLICE + i];
    v = fmaxf(v, 0.f);
    out[i] = v;
    __shared__ float cs[64];
    if (tid < 64) cs[tid] = 0.f;
    __syncthreads();
    atomicAdd(&cs[tid & 63], v);
    __syncthreads();
    if (tid < 64) {
        int b = blockIdx.x >> 7;               // 16 rows per block, 128 blocks/batch
        atomicAdd(&g_cent[b*FE + tid], cs[tid] * (1.f/NN));
    }
}

// ---------------- K3: per-row usq + global max|x-c| (vectorized) -------------
__global__ void k3_usq(const float* __restrict__ xemb) {
    int tid = threadIdx.x;                     // 256
    int row = blockIdx.x * 64 + (tid >> 2);    // 64 blocks x 64 rows
    int q = tid & 3;                           // quarter of the row (16 floats)
    int b = row >> 11;
    const float* p = xemb + (size_t)row*FE + q*16;
    const float* c = g_cent + b*FE + q*16;
    float sq = 0.f, av = 0.f;
    #pragma unroll
    for (int m = 0; m < 16; m += 4) {
        float4 t = *(const float4*)(p + m);
        float4 cc = *(const float4*)(c + m);
        float vx = t.x - cc.x, vy = t.y - cc.y, vz = t.z - cc.z, vw = t.w - cc.w;
        sq += vx*vx + vy*vy + vz*vz + vw*vw;
        av = fmaxf(av, fmaxf(fmaxf(fabsf(vx), fabsf(vy)), fmaxf(fabsf(vz), fabsf(vw))));
    }
    sq += __shfl_xor_sync(0xffffffffu, sq, 1);
    sq += __shfl_xor_sync(0xffffffffu, sq, 2);
    if (q == 0) g_usq[row] = sq;
    #pragma unroll
    for (int o = 1; o < 32; o <<= 1)
        av = fmaxf(av, __shfl_xor_sync(0xffffffffu, av, o));
    __shared__ float wm[8];
    if ((tid & 31) == 0) wm[tid >> 5] = av;
    __syncthreads();
    if (tid == 0) {
        float m = wm[0];
        #pragma unroll
        for (int w = 1; w < 8; ++w) m = fmaxf(m, wm[w]);
        atomicMax(&g_maxbits, __float_as_uint(m));
    }
}

// ---------------- K5: Gram + distances + sigmoid + edge_index ----------------
// BM=128(i) x BN=64(j), K=64, 256 threads, 8x4 fma2 microtile.
// Epilogue also emits edge_index rows/cols (pure index functions).
__global__ void __launch_bounds__(256) k5_gram(const float* __restrict__ xemb,
                        const float* __restrict__ temp, const float* __restrict__ thr,
                        float* __restrict__ out) {
    __shared__ float Ti[128][64];      // [i][e^swz(i)] centered, 32KB
    __shared__ float Tj[64][64];       // [j][e^swz(j)] centered, 16KB
    __shared__ float usqi[128], usqj[64];
    int b = blockIdx.z;
    int i0 = blockIdx.y * 128, j0 = blockIdx.x * 64;
    int tid = threadIdx.x;
    const float* Xb = xemb + (size_t)b*NN*FE;
    #pragma unroll
    for (int v = 0; v < 8; ++v) {      // Ti fill: 128 rows x 64 e
        int idx = tid + v*256;
        int row = idx >> 4, e4 = (idx & 15) * 4;
        float4 c = *(const float4*)&g_cent[b*FE + e4];
        float4 t = *(const float4*)(Xb + (size_t)(i0 + row)*FE + e4);
        t.x -= c.x; t.y -= c.y; t.z -= c.z; t.w -= c.w;
        int f = swz(row);
        *(float2*)&Ti[row][(e4    ) ^ f] = make_float2(t.x, t.y);
        *(float2*)&Ti[row][(e4 + 2) ^ f] = make_float2(t.z, t.w);
    }
    #pragma unroll
    for (int v = 0; v < 4; ++v) {      // Tj fill: 64 rows x 64 e
        int idx = tid + v*256;
        int row = idx >> 4, e4 = (idx & 15) * 4;
        float4 c = *(const float4*)&g_cent[b*FE + e4];
        float4 t = *(const float4*)(Xb + (size_t)(j0 + row)*FE + e4);
        t.x -= c.x; t.y -= c.y; t.z -= c.z; t.w -= c.w;
        int f = swz(row);
        *(float2*)&Tj[row][(e4    ) ^ f] = make_float2(t.x, t.y);
        *(float2*)&Tj[row][(e4 + 2) ^ f] = make_float2(t.z, t.w);
    }
    if (tid < 128) usqi[tid] = g_usq[b*NN + i0 + tid];
    else if (tid < 192) usqj[tid - 128] = g_usq[b*NN + j0 + (tid - 128)];
    __syncthreads();

    int ty = tid >> 4, tx = tid & 15;
    int ri = ty * 8, ej = tx * 4;
    int fA = ((2*ty) & 15) * 2, fB = ((2*ty + 1) & 15) * 2, fb = 2 * tx;
    ull acc[8][4];
    #pragma unroll
    for (int i = 0; i < 8; ++i)
        #pragma unroll
        for (int j = 0; j < 4; ++j) acc[i][j] = 0ull;

    #pragma unroll
    for (int kk = 0; kk < 64; kk += 2) {
        ull a2[8], b2[4];
        #pragma unroll
        for (int i = 0; i < 8; ++i)
            a2[i] = *(const ull*)&Ti[ri + i][kk ^ (i < 4 ? fA : fB)];
        #pragma unroll
        for (int j = 0; j < 4; ++j)
            b2[j] = *(const ull*)&Tj[ej + j][kk ^ fb];
        #pragma unroll
        for (int i = 0; i < 8; ++i)
            #pragma unroll
            for (int j = 0; j < 4; ++j)
                acc[i][j] = fma2(a2[i], b2[j], acc[i][j]);
    }

    float mx = __uint_as_float(g_maxbits);
    float s = 0.9f / mx, s2 = s * s;
    float T = *temp, TH = fabsf(*thr);
    float* Wgt  = out + OFF_WGT + (size_t)b*NN*NN;
    float* Rows = out + OFF_ROWS;
    float* Cols = out + OFF_ROWS + BN2;
    float cbase = (float)(j0 + ej + NN*b);
    float4 cv = make_float4(cbase, cbase + 1.f, cbase + 2.f, cbase + 3.f);
    #pragma unroll
    for (int i = 0; i < 8; ++i) {
        int gi = i0 + ri + i;
        float ui = usqi[ri + i];
        float w[4];
        #pragma unroll
        for (int j = 0; j < 4; ++j) {
            float d = s2 * (ui + usqj[ej + j] - 2.f * fsum2(acc[i][j]));
            d = fmaxf(d, 0.f);
            float z = T * (TH - d);
            w[j] = __fdividef(1.f, 1.f + __expf(-z));
        }
        size_t gk = ((size_t)b*NN + gi)*NN + j0 + ej;
        *(float4*)(Wgt + (size_t)gi*NN + j0 + ej) = make_float4(w[0], w[1], w[2], w[3]);
        float rv = (float)(b*NN + gi);
        *(float4*)(Rows + gk) = make_float4(rv, rv, rv, rv);
        *(float4*)(Cols + gk) = cv;
    }
}

extern "C" void kernel_launch(void* const* d_in, const int* in_sizes, int n_in,
                              void* d_out, int out_size) {
    const float* x    = (const float*)d_in[0];
    const float* A    = (const float*)d_in[1];
    const float* W    = (const float*)d_in[2];
    const float* bias = (const float*)d_in[3];
    const float* temp = (const float*)d_in[4];
    const float* thr  = (const float*)d_in[5];
    float* out = (float*)d_out;

    k0_xw<<<NB*NN/16, 256>>>(x, W);
    k1_gemm<<<dim3(NN/128, KS, NB), 256>>>(A);
    k1b_bias<<<(NB*NN*FE)/1024, 1024>>>(bias, out);
    k3_usq<<<NB*NN/64, 256>>>(out);
    k5_gram<<<dim3(NN/64, NN/128, NB), 256>>>(out, temp, thr, out);
}

// round 5
// speedup vs baseline: 1.2801x; 1.0241x over previous
#include <cuda_runtime.h>

#define NB 2
#define NN 2048
#define FIN 128
#define FE 64
#define BN2 (NB*NN*NN)                 // 8388608
#define OFF_ROWS 262144
#define OFF_WGT  (262144 + 2*BN2)      // 17039360
#define KS 8                           // k-split for K1
#define SLICE (NB*NN*FE)               // 262144

typedef unsigned long long ull;

__device__ float g_xw[NB*NN*FE];       // x @ W
__device__ float g_part[KS*NB*NN*FE];  // k-split partials of A@xw
__device__ float g_cent[NB*FE];
__device__ float g_usq[NB*NN];         // unscaled sum((x-c)^2) per row
__device__ unsigned int g_maxbits;     // max |x-c| as float bits

// packed fp32x2 FMA (Blackwell): d = a*b + c elementwise on float pairs
__device__ __forceinline__ ull fma2(ull a, ull b, ull c) {
    ull d;
    asm("fma.rn.f32x2 %0, %1, %2, %3;" : "=l"(d) : "l"(a), "l"(b), "l"(c));
    return d;
}
__device__ __forceinline__ float fsum2(ull v) {
    float2 f = *reinterpret_cast<float2*>(&v);
    return f.x + f.y;
}
// row-dependent swizzle of the k-contiguous column index (keeps 8B alignment)
__device__ __forceinline__ int swz(int r) { return ((r >> 2) & 15) * 2; }

// ---------------- K0: xw = x @ W  (tiny GEMM, W resident in smem) ------------
__global__ void k0_xw(const float* __restrict__ x, const float* __restrict__ W) {
    __shared__ float Wsh[FIN*FE];      // 32 KB
    __shared__ float xsh[4][FIN];
    int tid = threadIdx.x;             // 256
    if (blockIdx.x == 0) {             // zero accumulators for later kernels
        if (tid < NB*FE) g_cent[tid] = 0.f;
        if (tid == 128) g_maxbits = 0u;
    }
    for (int i = tid; i < FIN*FE; i += 256) Wsh[i] = W[i];
    int rowBase = blockIdx.x * 16;
    int rloc = tid >> 6, e = tid & 63;
    for (int pass = 0; pass < 4; ++pass) {
        __syncthreads();
        int r0 = rowBase + pass * 4;
        for (int i = tid; i < 4*FIN; i += 256)
            xsh[i >> 7][i & 127] = x[(size_t)r0*FIN + i];
        __syncthreads();
        float acc = 0.f;
        #pragma unroll
        for (int k = 0; k < FIN; ++k)
            acc = fmaf(xsh[rloc][k], Wsh[k*FE + e], acc);
        g_xw[(size_t)(r0 + rloc)*FE + e] = acc;
    }
}

// ---------------- K1: partial = A @ xw  (BM=128, BN=64, BK=32, ksplit=8) -----
// 256 threads, 8x4 fma2 microtile, swizzled k-contiguous tiles, LDS.64 operands.
__global__ void __launch_bounds__(256) k1_gemm(const float* __restrict__ A) {
    __shared__ float As[128][32];      // [row][k^swz(row)] 16KB
    __shared__ float Xs[64][32];       // [e][k^swz(e)]     8KB
    int b = blockIdx.z, ks = blockIdx.y;
    int i0 = blockIdx.x * 128;
    int tid = threadIdx.x;
    int ty = tid >> 4, tx = tid & 15;
    int ri = ty * 8, ej = tx * 4;
    int fA = ((2*ty) & 15) * 2, fB = ((2*ty + 1) & 15) * 2, fb = 2 * tx;
    const float* Ab = A + (size_t)b*NN*NN;
    const float* Xb = g_xw + (size_t)b*NN*FE;
    ull acc[8][4];
    #pragma unroll
    for (int i = 0; i < 8; ++i)
        #pragma unroll
        for (int j = 0; j < 4; ++j) acc[i][j] = 0ull;

    int kbeg = ks * (NN/KS);
    for (int k0 = kbeg; k0 < kbeg + NN/KS; k0 += 32) {
        #pragma unroll
        for (int v = 0; v < 4; ++v) {          // A tile: 128 rows x 32 k
            int idx = tid + v*256;
            int row = idx >> 3, kq = (idx & 7) * 4;
            float4 t = *(const float4*)(Ab + (size_t)(i0 + row)*NN + k0 + kq);
            int f = swz(row);
            *(float2*)&As[row][(kq    ) ^ f] = make_float2(t.x, t.y);
            *(float2*)&As[row][(kq + 2) ^ f] = make_float2(t.z, t.w);
        }
        #pragma unroll
        for (int v = 0; v < 2; ++v) {          // X tile: 32 k x 64 e -> [e][k]
            int idx = tid + v*256;
            int kk = idx >> 4, e4 = (idx & 15) * 4;
            float4 t = *(const float4*)(Xb + (size_t)(k0 + kk)*FE + e4);
            Xs[e4+0][kk ^ swz(e4+0)] = t.x;
            Xs[e4+1][kk ^ swz(e4+1)] = t.y;
            Xs[e4+2][kk ^ swz(e4+2)] = t.z;
            Xs[e4+3][kk ^ swz(e4+3)] = t.w;
        }
        __syncthreads();
        #pragma unroll
        for (int kk = 0; kk < 32; kk += 2) {
            ull a2[8], b2[4];
            #pragma unroll
            for (int i = 0; i < 8; ++i)
                a2[i] = *(const ull*)&As[ri + i][kk ^ (i < 4 ? fA : fB)];
            #pragma unroll
            for (int j = 0; j < 4; ++j)
                b2[j] = *(const ull*)&Xs[ej + j][kk ^ fb];
            #pragma unroll
            for (int i = 0; i < 8; ++i)
                #pragma unroll
                for (int j = 0; j < 4; ++j)
                    acc[i][j] = fma2(a2[i], b2[j], acc[i][j]);
        }
        __syncthreads();
    }
    float* P = g_part + (size_t)ks*SLICE + (size_t)b*NN*FE;
    #pragma unroll
    for (int i = 0; i < 8; ++i) {
        float4 v = make_float4(fsum2(acc[i][0]), fsum2(acc[i][1]),
                               fsum2(acc[i][2]), fsum2(acc[i][3]));
        *(float4*)(P + (size_t)(i0 + ri + i)*FE + ej) = v;
    }
}

// ---------------- K1b: x_emb = relu(sum partials + bias), + centroid sums ----
__global__ void k1b_bias(const float* __restrict__ bias, float* __restrict__ out) {
    int tid = threadIdx.x;                     // 1024
    int i = blockIdx.x * 1024 + tid;           // 256 blocks cover 262144
    float v = bias[i & 63];
    #pragma unroll
    for (int s = 0; s < KS; ++s) v += g_part[(size_t)s*SLICE + i];
    v = fmaxf(v, 0.f);
    out[i] = v;
    __shared__ float cs[64];
    if (tid < 64) cs[tid] = 0.f;
    __syncthreads();
    atomicAdd(&cs[tid & 63], v);
    __syncthreads();
    if (tid < 64) {
        int b = blockIdx.x >> 7;               // 16 rows per block, 128 blocks/batch
        atomicAdd(&g_cent[b*FE + tid], cs[tid] * (1.f/NN));
    }
}

// ---------------- K3: per-row usq + global max|x-c| (vectorized) -------------
__global__ void k3_usq(const float* __restrict__ xemb) {
    int tid = threadIdx.x;                     // 256
    int row = blockIdx.x * 64 + (tid >> 2);    // 64 blocks x 64 rows
    int q = tid & 3;                           // quarter of the row (16 floats)
    int b = row >> 11;
    const float* p = xemb + (size_t)row*FE + q*16;
    const float* c = g_cent + b*FE + q*16;
    float sq = 0.f, av = 0.f;
    #pragma unroll
    for (int m = 0; m < 16; m += 4) {
        float4 t = *(const float4*)(p + m);
        float4 cc = *(const float4*)(c + m);
        float vx = t.x - cc.x, vy = t.y - cc.y, vz = t.z - cc.z, vw = t.w - cc.w;
        sq += vx*vx + vy*vy + vz*vz + vw*vw;
        av = fmaxf(av, fmaxf(fmaxf(fabsf(vx), fabsf(vy)), fmaxf(fabsf(vz), fabsf(vw))));
    }
    sq += __shfl_xor_sync(0xffffffffu, sq, 1);
    sq += __shfl_xor_sync(0xffffffffu, sq, 2);
    if (q == 0) g_usq[row] = sq;
    #pragma unroll
    for (int o = 1; o < 32; o <<= 1)
        av = fmaxf(av, __shfl_xor_sync(0xffffffffu, av, o));
    __shared__ float wm[8];
    if ((tid & 31) == 0) wm[tid >> 5] = av;
    __syncthreads();
    if (tid == 0) {
        float m = wm[0];
        #pragma unroll
        for (int w = 1; w < 8; ++w) m = fmaxf(m, wm[w]);
        atomicMax(&g_maxbits, __float_as_uint(m));
    }
}

// ---------------- K5: Gram + distances + sigmoid + edge_index ----------------
// BM=128(i) x BN=64(j), K=64, 256 threads, 8x4 fma2 microtile.
// Epilogue also emits edge_index rows/cols (pure index functions).
__global__ void __launch_bounds__(256) k5_gram(const float* __restrict__ xemb,
                        const float* __restrict__ temp, const float* __restrict__ thr,
                        float* __restrict__ out) {
    __shared__ float Ti[128][64];      // [i][e^swz(i)] centered, 32KB
    __shared__ float Tj[64][64];       // [j][e^swz(j)] centered, 16KB
    __shared__ float usqi[128], usqj[64];
    int b = blockIdx.z;
    int i0 = blockIdx.y * 128, j0 = blockIdx.x * 64;
    int tid = threadIdx.x;
    const float* Xb = xemb + (size_t)b*NN*FE;
    #pragma unroll
    for (int v = 0; v < 8; ++v) {      // Ti fill: 128 rows x 64 e
        int idx = tid + v*256;
        int row = idx >> 4, e4 = (idx & 15) * 4;
        float4 c = *(const float4*)&g_cent[b*FE + e4];
        float4 t = *(const float4*)(Xb + (size_t)(i0 + row)*FE + e4);
        t.x -= c.x; t.y -= c.y; t.z -= c.z; t.w -= c.w;
        int f = swz(row);
        *(float2*)&Ti[row][(e4    ) ^ f] = make_float2(t.x, t.y);
        *(float2*)&Ti[row][(e4 + 2) ^ f] = make_float2(t.z, t.w);
    }
    #pragma unroll
    for (int v = 0; v < 4; ++v) {      // Tj fill: 64 rows x 64 e
        int idx = tid + v*256;
        int row = idx >> 4, e4 = (idx & 15) * 4;
        float4 c = *(const float4*)&g_cent[b*FE + e4];
        float4 t = *(const float4*)(Xb + (size_t)(j0 + row)*FE + e4);
        t.x -= c.x; t.y -= c.y; t.z -= c.z; t.w -= c.w;
        int f = swz(row);
        *(float2*)&Tj[row][(e4    ) ^ f] = make_float2(t.x, t.y);
        *(float2*)&Tj[row][(e4 + 2) ^ f] = make_float2(t.z, t.w);
    }
    if (tid < 128) usqi[tid] = g_usq[b*NN + i0 + tid];
    else if (tid < 192) usqj[tid - 128] = g_usq[b*NN + j0 + (tid - 128)];
    __syncthreads();

    int ty = tid >> 4, tx = tid & 15;
    int ri = ty * 8, ej = tx * 4;
    int fA = ((2*ty) & 15) * 2, fB = ((2*ty + 1) & 15) * 2, fb = 2 * tx;
    ull acc[8][4];
    #pragma unroll
    for (int i = 0; i < 8; ++i)
        #pragma unroll
        for (int j = 0; j < 4; ++j) acc[i][j] = 0ull;

    #pragma unroll
    for (int kk = 0; kk < 64; kk += 2) {
        ull a2[8], b2[4];
        #pragma unroll
        for (int i = 0; i < 8; ++i)
            a2[i] = *(const ull*)&Ti[ri + i][kk ^ (i < 4 ? fA : fB)];
        #pragma unroll
        for (int j = 0; j < 4; ++j)
            b2[j] = *(const ull*)&Tj[ej + j][kk ^ fb];
        #pragma unroll
        for (int i = 0; i < 8; ++i)
            #pragma unroll
            for (int j = 0; j < 4; ++j)
                acc[i][j] = fma2(a2[i], b2[j], acc[i][j]);
    }

    float mx = __uint_as_float(g_maxbits);
    float s = 0.9f / mx, s2 = s * s;
    float T = *temp, TH = fabsf(*thr);
    float* Wgt  = out + OFF_WGT + (size_t)b*NN*NN;
    float* Rows = out + OFF_ROWS;
    float* Cols = out + OFF_ROWS + BN2;
    float cbase = (float)(j0 + ej + NN*b);
    float4 cv = make_float4(cbase, cbase + 1.f, cbase + 2.f, cbase + 3.f);
    #pragma unroll
    for (int i = 0; i < 8; ++i) {
        int gi = i0 + ri + i;
        float ui = usqi[ri + i];
        float w[4];
        #pragma unroll
        for (int j = 0; j < 4; ++j) {
            float d = s2 * (ui + usqj[ej + j] - 2.f * fsum2(acc[i][j]));
            d = fmaxf(d, 0.f);
            float z = T * (TH - d);
            w[j] = __fdividef(1.f, 1.f + __expf(-z));
        }
        size_t gk = ((size_t)b*NN + gi)*NN + j0 + ej;
        *(float4*)(Wgt + (size_t)gi*NN + j0 + ej) = make_float4(w[0], w[1], w[2], w[3]);
        float rv = (float)(b*NN + gi);
        *(float4*)(Rows + gk) = make_float4(rv, rv, rv, rv);
        *(float4*)(Cols + gk) = cv;
    }
}

extern "C" void kernel_launch(void* const* d_in, const int* in_sizes, int n_in,
                              void* d_out, int out_size) {
    const float* x    = (const float*)d_in[0];
    const float* A    = (const float*)d_in[1];
    const float* W    = (const float*)d_in[2];
    const float* bias = (const float*)d_in[3];
    const float* temp = (const float*)d_in[4];
    const float* thr  = (const float*)d_in[5];
    float* out = (float*)d_out;

    k0_xw<<<NB*NN/16, 256>>>(x, W);
    k1_gemm<<<dim3(NN/128, KS, NB), 256>>>(A);
    k1b_bias<<<(NB*NN*FE)/1024, 1024>>>(bias, out);
    k3_usq<<<NB*NN/64, 256>>>(out);
    k5_gram<<<dim3(NN/64, NN/128, NB), 256>>>(out, temp, thr, out);
}

// round 7
// speedup vs baseline: 1.5682x; 1.2250x over previous
#include <cuda_runtime.h>
#include <cuda_bf16.h>

#define NB 2
#define NN 2048
#define FIN 128
#define FE 64
#define BN2 (NB*NN*NN)                 // 8388608
#define OFF_ROWS 262144
#define OFF_WGT  (262144 + 2*BN2)      // 17039360
#define KS 4
#define SLICE (NB*NN*FE)               // 262144

typedef unsigned int u32;
typedef unsigned long long u64;

__device__ float g_xw[NB*NN*FE];                  // x @ W (fp32)
__device__ float g_part[KS*NB*NN*FE];             // k-split partials of A@xw
__device__ __align__(16) u32 g_xwt_h[NB*FE*NN/2]; // bf16x2 hi, transposed [b*64+e][n/2]
__device__ __align__(16) u32 g_xwt_l[NB*FE*NN/2]; // bf16x2 lo
__device__ __align__(16) u32 g_csh[NB*NN*FE/2];   // centered x_emb bf16x2 hi [row][e/2]
__device__ __align__(16) u32 g_csl[NB*NN*FE/2];   // centered lo
__device__ float g_cent[NB*FE];
__device__ float g_usq[NB*NN];
__device__ u32 g_maxbits;

// ---------------- warp-MMA helpers (base ISA: sm_80+) ------------------------
__device__ __forceinline__ u32 smem_u32(const void* p) {
    u32 a;
    asm("{ .reg .u64 t; cvta.to.shared.u64 t, %1; cvt.u32.u64 %0, t; }"
        : "=r"(a) : "l"(p));
    return a;
}
// tile rows are 128 B; col8 indexes 16B groups; XOR swizzle on (row&7)
__device__ __forceinline__ u32 ldm_addr(u32 base, int row, int col8) {
    return base + row*128 + ((col8 ^ (row & 7)) << 4);
}
__device__ __forceinline__ void ldmx4(u32 a, u32& r0, u32& r1, u32& r2, u32& r3) {
    asm volatile("ldmatrix.sync.aligned.m8n8.x4.shared.b16 {%0,%1,%2,%3}, [%4];"
        : "=r"(r0), "=r"(r1), "=r"(r2), "=r"(r3) : "r"(a) : "memory");
}
__device__ __forceinline__ void mma16816(float* d, const u32* a, u32 b0, u32 b1) {
    asm volatile("mma.sync.aligned.m16n8k16.row.col.f32.bf16.bf16.f32 "
        "{%0,%1,%2,%3}, {%4,%5,%6,%7}, {%8,%9}, {%0,%1,%2,%3};"
        : "+f"(d[0]), "+f"(d[1]), "+f"(d[2]), "+f"(d[3])
        : "r"(a[0]), "r"(a[1]), "r"(a[2]), "r"(a[3]), "r"(b0), "r"(b1));
}
__device__ __forceinline__ void split2(float a, float b, u32& H, u32& L) {
    __nv_bfloat16 ha = __float2bfloat16(a), hb = __float2bfloat16(b);
    float ra = a - __bfloat162float(ha), rb = b - __bfloat162float(hb);
    __nv_bfloat162 hh; hh.x = ha; hh.y = hb;
    __nv_bfloat162 ll; ll.x = __float2bfloat16(ra); ll.y = __float2bfloat16(rb);
    H = *(u32*)&hh; L = *(u32*)&ll;
}

// ---------------- K0: xw = x @ W + zero accumulators -------------------------
__global__ void k0_xw(const float* __restrict__ x, const float* __restrict__ W) {
    __shared__ float Wsh[FIN*FE];
    __shared__ float xsh[4][FIN];
    int tid = threadIdx.x;             // 256
    if (blockIdx.x == 0) {
        if (tid < NB*FE) g_cent[tid] = 0.f;
        if (tid == 128) g_maxbits = 0u;
    }
    for (int i = tid; i < FIN*FE; i += 256) Wsh[i] = W[i];
    int rowBase = blockIdx.x * 16;
    int rloc = tid >> 6, e = tid & 63;
    for (int pass = 0; pass < 4; ++pass) {
        __syncthreads();
        int r0 = rowBase + pass * 4;
        for (int i = tid; i < 4*FIN; i += 256)
            xsh[i >> 7][i & 127] = x[(size_t)r0*FIN + i];
        __syncthreads();
        float acc = 0.f;
        #pragma unroll
        for (int k = 0; k < FIN; ++k)
            acc = fmaf(xsh[rloc][k], Wsh[k*FE + e], acc);
        g_xw[(size_t)(r0 + rloc)*FE + e] = acc;
    }
}

// ---------------- K0b: transpose + bf16-split xw -> g_xwt_{h,l}[e][n] --------
__global__ void k0b_tr() {
    __shared__ float st[64][65];
    int tid = threadIdx.x;             // 256
    int b = blockIdx.y, n0 = blockIdx.x * 64;
    #pragma unroll
    for (int v = 0; v < 4; ++v) {
        int idx = tid + v*256;
        int n = idx >> 4, e4 = (idx & 15) * 4;
        float4 t = *(const float4*)(g_xw + (size_t)(b*NN + n0 + n)*FE + e4);
        st[n][e4] = t.x; st[n][e4+1] = t.y; st[n][e4+2] = t.z; st[n][e4+3] = t.w;
    }
    __syncthreads();
    int e = tid >> 2, q = tid & 3;
    u32 H[8], L[8];
    #pragma unroll
    for (int p = 0; p < 8; ++p) {
        int n = q*16 + p*2;
        split2(st[n][e], st[n+1][e], H[p], L[p]);
    }
    u32 base = (u32)(b*FE + e) * (NN/2) + (u32)((n0 + q*16) >> 1);
    *(uint4*)(g_xwt_h + base)     = make_uint4(H[0], H[1], H[2], H[3]);
    *(uint4*)(g_xwt_h + base + 4) = make_uint4(H[4], H[5], H[6], H[7]);
    *(uint4*)(g_xwt_l + base)     = make_uint4(L[0], L[1], L[2], L[3]);
    *(uint4*)(g_xwt_l + base + 4) = make_uint4(L[4], L[5], L[6], L[7]);
}

// ---------------- K1: partials of A @ xw via warp-MMA bf16-split -------------
// CTA 128x64, k-split 4 (K=512 each), chunks of 64. Warps 4x2, warp tile 32x32.
__global__ void __launch_bounds__(256) k1_mma(const float* __restrict__ A) {
    extern __shared__ __align__(16) char dsm[];
    int tid = threadIdx.x, wid = tid >> 5, lane = tid & 31;
    int wy = wid & 3, wx = wid >> 2;
    int sub = lane >> 3, lr = lane & 7;
    int b = blockIdx.z, ks = blockIdx.y, i0 = blockIdx.x * 128;

    u32 raw = smem_u32(dsm);
    u32 ab = (raw + 1023u) & ~1023u;
    char* AB = dsm + (ab - raw);
    char* AH = AB;                 // 16K: A-hi 128x64 bf16
    char* AL = AB + 16384;         // 16K
    char* XH = AB + 32768;         // 8K: X-hi 64x64 bf16
    char* XL = AB + 40960;         // 8K
    u32 abH = ab, abL = ab + 16384, xbH = ab + 32768, xbL = ab + 40960;

    const float* Ab = A + (size_t)b*NN*NN;
    float acc[2][4][4];
    #pragma unroll
    for (int m = 0; m < 2; ++m)
        #pragma unroll
        for (int n = 0; n < 4; ++n)
            #pragma unroll
            for (int q = 0; q < 4; ++q) acc[m][n][q] = 0.f;

    int kbeg = ks * (NN/KS);
    for (int it = 0; it < (NN/KS)/64; ++it) {
        int k0 = kbeg + it * 64;
        #pragma unroll
        for (int v = 0; v < 8; ++v) {          // A tile: 128 rows x 64 k, split
            int idx = tid + v*256;
            int row = idx >> 4, kq = (idx & 15) * 4;
            float4 t = *(const float4*)(Ab + (size_t)(i0 + row)*NN + k0 + kq);
            u32 h01, l01, h23, l23;
            split2(t.x, t.y, h01, l01);
            split2(t.z, t.w, h23, l23);
            int off = row*128 + kq*2; off ^= (off >> 3) & 0x70;
            *(u64*)(AH + off) = (u64)h01 | ((u64)h23 << 32);
            *(u64*)(AL + off) = (u64)l01 | ((u64)l23 << 32);
        }
        #pragma unroll
        for (int v = 0; v < 2; ++v) {          // X tile: 64 e-rows x 64 k, pre-split
            int idx = tid + v*256;
            int e = idx >> 3, q = idx & 7;
            u32 srci = (u32)(b*FE + e) * (NN/2) + (u32)(k0 >> 1);
            uint4 vh = *((const uint4*)(g_xwt_h + srci) + q);
            uint4 vl = *((const uint4*)(g_xwt_l + srci) + q);
            int off = e*128 + q*16; off ^= (off >> 3) & 0x70;
            *(uint4*)(XH + off) = vh;
            *(uint4*)(XL + off) = vl;
        }
        __syncthreads();
        #pragma unroll
        for (int kp = 0; kp < 4; ++kp) {       // 4 k-steps of 16
            int c8 = kp * 2;
            u32 aH[2][4], aL[2][4];
            #pragma unroll
            for (int mt = 0; mt < 2; ++mt) {
                int r = wy*32 + mt*16 + lr + (sub & 1)*8;
                int cc = c8 + (sub >> 1);
                ldmx4(ldm_addr(abH, r, cc), aH[mt][0], aH[mt][1], aH[mt][2], aH[mt][3]);
                ldmx4(ldm_addr(abL, r, cc), aL[mt][0], aL[mt][1], aL[mt][2], aL[mt][3]);
            }
            #pragma unroll
            for (int np = 0; np < 2; ++np) {   // pairs of n-tiles
                int rb = wx*32 + np*16 + lr + (sub >> 1)*8;
                int cb = c8 + (sub & 1);
                u32 bh[4], bl[4];
                ldmx4(ldm_addr(xbH, rb, cb), bh[0], bh[1], bh[2], bh[3]);
                ldmx4(ldm_addr(xbL, rb, cb), bl[0], bl[1], bl[2], bl[3]);
                #pragma unroll
                for (int mt = 0; mt < 2; ++mt)
                    #pragma unroll
                    for (int t = 0; t < 2; ++t) {
                        float* d = acc[mt][np*2 + t];
                        mma16816(d, aH[mt], bh[2*t], bh[2*t+1]);
                        mma16816(d, aH[mt], bl[2*t], bl[2*t+1]);
                        mma16816(d, aL[mt], bh[2*t], bh[2*t+1]);
                    }
            }
        }
        __syncthreads();
    }
    float* P = g_part + (size_t)ks*SLICE + (size_t)b*NN*FE;
    #pragma unroll
    for (int mt = 0; mt < 2; ++mt) {
        int gi = i0 + wy*32 + mt*16 + (lane >> 2);
        #pragma unroll
        for (int nt = 0; nt < 4; ++nt) {
            int c = wx*32 + nt*8 + 2*(lane & 3);
            float* d = acc[mt][nt];
            *(float2*)(P + (size_t)gi*FE + c)       = make_float2(d[0], d[1]);
            *(float2*)(P + (size_t)(gi + 8)*FE + c) = make_float2(d[2], d[3]);
        }
    }
}

// ---------------- K1b: x_emb = relu(sum partials + bias), + centroid sums ----
__global__ void k1b_bias(const float* __restrict__ bias, float* __restrict__ out) {
    int tid = threadIdx.x;                     // 1024
    int i = blockIdx.x * 1024 + tid;           // 256 blocks cover 262144
    float v = bias[i & 63];
    #pragma unroll
    for (int s = 0; s < KS; ++s) v += g_part[(size_t)s*SLICE + i];
    v = fmaxf(v, 0.f);
    out[i] = v;
    __shared__ float cs[64];
    if (tid < 64) cs[tid] = 0.f;
    __syncthreads();
    atomicAdd(&cs[tid & 63], v);
    __syncthreads();
    if (tid < 64) {
        int b = blockIdx.x >> 7;
        atomicAdd(&g_cent[b*FE + tid], cs[tid] * (1.f/NN));
    }
}

// ---------------- K3: usq + max|x-c| + centered bf16 split -------------------
__global__ void k3_usq(const float* __restrict__ xemb) {
    int tid = threadIdx.x, w = tid >> 5, l = tid & 31;
    int row = blockIdx.x * 8 + w;      // grid 512
    int b = row >> 11;
    float2 t = *(const float2*)(xemb + (size_t)row*FE + 2*l);
    float2 c = *(const float2*)(g_cent + b*FE + 2*l);
    float v0 = t.x - c.x, v1 = t.y - c.y;
    u32 H, L;
    split2(v0, v1, H, L);
    g_csh[row*32 + l] = H;
    g_csl[row*32 + l] = L;
    float sq = v0*v0 + v1*v1;
    float av = fmaxf(fabsf(v0), fabsf(v1));
    #pragma unroll
    for (int o = 16; o; o >>= 1) {
        sq += __shfl_xor_sync(0xffffffffu, sq, o);
        av = fmaxf(av, __shfl_xor_sync(0xffffffffu, av, o));
    }
    if (l == 0) g_usq[row] = sq;
    __shared__ float wm[8];
    if (l == 0) wm[w] = av;
    __syncthreads();
    if (tid == 0) {
        float m = wm[0];
        #pragma unroll
        for (int i = 1; i < 8; ++i) m = fmaxf(m, wm[i]);
        atomicMax(&g_maxbits, __float_as_uint(m));
    }
}

__device__ __forceinline__ float sigw(float a, float ui, float uj,
                                      float s2, float T, float TH) {
    float dd = fmaxf(s2 * (ui + uj - 2.f*a), 0.f);
    float z = T * (TH - dd);
    return __fdividef(1.f, 1.f + __expf(-z));
}

// ---------------- K5: Gram via warp-MMA + distances + sigmoid + edge_index ---
// CTA 128x128, K=64. Warps 4x2, warp tile 32x64.
__global__ void __launch_bounds__(256) k5_mma(const float* __restrict__ temp,
                                              const float* __restrict__ thr,
                                              float* __restrict__ out) {
    extern __shared__ __align__(16) char dsm[];
    __shared__ float usqi[128], usqj[128];
    int tid = threadIdx.x, wid = tid >> 5, lane = tid & 31;
    int wy = wid & 3, wx = wid >> 2;
    int sub = lane >> 3, lr = lane & 7;
    int b = blockIdx.z, i0 = blockIdx.y * 128, j0 = blockIdx.x * 128;

    u32 raw = smem_u32(dsm);
    u32 ab = (raw + 1023u) & ~1023u;
    char* AB = dsm + (ab - raw);
    u32 tiH = ab, tiL = ab + 16384, tjH = ab + 32768, tjL = ab + 49152;

    #pragma unroll
    for (int t = 0; t < 4; ++t) {      // TiH, TiL, TjH, TjL (128 rows x 128 B)
        int rb = (t < 2) ? i0 : j0;
        const u32* src = (t & 1) ? g_csl : g_csh;
        char* dst = AB + t*16384;
        #pragma unroll
        for (int v = 0; v < 4; ++v) {
            int idx = tid + v*256;
            int row = idx >> 3, q = idx & 7;
            uint4 val = *((const uint4*)(src + ((size_t)(b*NN + rb + row) << 5)) + q);
            int off = row*128 + q*16; off ^= (off >> 3) & 0x70;
            *(uint4*)(dst + off) = val;
        }
    }
    if (tid < 128) usqi[tid] = g_usq[b*NN + i0 + tid];
    else           usqj[tid-128] = g_usq[b*NN + j0 + (tid-128)];
    __syncthreads();

    float acc[2][8][4];
    #pragma unroll
    for (int m = 0; m < 2; ++m)
        #pragma unroll
        for (int n = 0; n < 8; ++n)
            #pragma unroll
            for (int q = 0; q < 4; ++q) acc[m][n][q] = 0.f;

    #pragma unroll
    for (int kp = 0; kp < 4; ++kp) {
        int c8 = kp * 2;
        u32 aH[2][4], aL[2][4];
        #pragma unroll
        for (int mt = 0; mt < 2; ++mt) {
            int r = wy*32 + mt*16 + lr + (sub & 1)*8;
            int cc = c8 + (sub >> 1);
            ldmx4(ldm_addr(tiH, r, cc), aH[mt][0], aH[mt][1], aH[mt][2], aH[mt][3]);
            ldmx4(ldm_addr(tiL, r, cc), aL[mt][0], aL[mt][1], aL[mt][2], aL[mt][3]);
        }
        #pragma unroll
        for (int np = 0; np < 4; ++np) {
            int rb = wx*64 + np*16 + lr + (sub >> 1)*8;
            int cb = c8 + (sub & 1);
            u32 bh[4], bl[4];
            ldmx4(ldm_addr(tjH, rb, cb), bh[0], bh[1], bh[2], bh[3]);
            ldmx4(ldm_addr(tjL, rb, cb), bl[0], bl[1], bl[2], bl[3]);
            #pragma unroll
            for (int mt = 0; mt < 2; ++mt)
                #pragma unroll
                for (int t = 0; t < 2; ++t) {
                    float* d = acc[mt][np*2 + t];
                    mma16816(d, aH[mt], bh[2*t], bh[2*t+1]);
                    mma16816(d, aH[mt], bl[2*t], bl[2*t+1]);
                    mma16816(d, aL[mt], bh[2*t], bh[2*t+1]);
                }
        }
    }

    float s = 0.9f / __uint_as_float(g_maxbits);
    float s2 = s * s;
    float T = *temp, TH = fabsf(*thr);
    float* WgB = out + OFF_WGT + (size_t)b*NN*NN;
    float* RoB = out + OFF_ROWS;
    float* CoB = out + OFF_ROWS + BN2;
    #pragma unroll
    for (int mt = 0; mt < 2; ++mt) {
        int li = wy*32 + mt*16 + (lane >> 2);
        int gi0 = i0 + li, gi8 = gi0 + 8;
        float ui0 = usqi[li], ui8 = usqi[li + 8];
        float rv0 = (float)(b*NN + gi0), rv8 = (float)(b*NN + gi8);
        size_t w0 = (size_t)gi0*NN + j0, w8 = (size_t)gi8*NN + j0;
        size_t e0 = ((size_t)b*NN + gi0)*NN + j0, e8 = ((size_t)b*NN + gi8)*NN + j0;
        #pragma unroll
        for (int nt = 0; nt < 8; ++nt) {
            int c = wx*64 + nt*8 + 2*(lane & 3);
            float uj0 = usqj[c], uj1 = usqj[c + 1];
            float* d = acc[mt][nt];
            float cj = (float)(j0 + c + NN*b);
            *(float2*)(WgB + w0 + c) = make_float2(sigw(d[0], ui0, uj0, s2, T, TH),
                                                   sigw(d[1], ui0, uj1, s2, T, TH));
            *(float2*)(WgB + w8 + c) = make_float2(sigw(d[2], ui8, uj0, s2, T, TH),
                                                   sigw(d[3], ui8, uj1, s2, T, TH));
            *(float2*)(RoB + e0 + c) = make_float2(rv0, rv0);
            *(float2*)(RoB + e8 + c) = make_float2(rv8, rv8);
            *(float2*)(CoB + e0 + c) = make_float2(cj, cj + 1.f);
            *(float2*)(CoB + e8 + c) = make_float2(cj, cj + 1.f);
        }
    }
}

extern "C" void kernel_launch(void* const* d_in, const int* in_sizes, int n_in,
                              void* d_out, int out_size) {
    const float* x    = (const float*)d_in[0];
    const float* A    = (const float*)d_in[1];
    const float* W    = (const float*)d_in[2];
    const float* bias = (const float*)d_in[3];
    const float* temp = (const float*)d_in[4];
    const float* thr  = (const float*)d_in[5];
    float* out = (float*)d_out;

    cudaFuncSetAttribute(k1_mma, cudaFuncAttributeMaxDynamicSharedMemorySize, 50176);
    cudaFuncSetAttribute(k5_mma, cudaFuncAttributeMaxDynamicSharedMemorySize, 66560);

    k0_xw<<<NB*NN/16, 256>>>(x, W);
    k0b_tr<<<dim3(NN/64, NB), 256>>>();
    k1_mma<<<dim3(NN/128, KS, NB), 256, 50176>>>(A);
    k1b_bias<<<(NB*NN*FE)/1024, 1024>>>(bias, out);
    k3_usq<<<NB*NN/8, 256>>>(out);
    k5_mma<<<dim3(NN/128, NN/128, NB), 256, 66560>>>(temp, thr, out);
}

// round 8
// speedup vs baseline: 1.8890x; 1.2046x over previous
#include <cuda_runtime.h>
#include <cuda_bf16.h>

#define NB 2
#define NN 2048
#define FIN 128
#define FE 64
#define BN2 (NB*NN*NN)                 // 8388608
#define OFF_ROWS 262144
#define OFF_WGT  (262144 + 2*BN2)      // 17039360
#define KS 4
#define SLICE (NB*NN*FE)               // 262144

typedef unsigned int u32;
typedef unsigned long long u64;

__device__ float g_part[KS*NB*NN*FE];             // k-split partials of A@xw
__device__ __align__(16) u32 g_xwt_h[NB*FE*NN/2]; // bf16x2 hi, transposed [b*64+e][n/2]
__device__ __align__(16) u32 g_xwt_l[NB*FE*NN/2]; // bf16x2 lo
__device__ __align__(16) u32 g_csh[NB*NN*FE/2];   // centered x_emb bf16x2 hi [row][e/2]
__device__ __align__(16) u32 g_csl[NB*NN*FE/2];   // centered lo
__device__ float g_cent[NB*FE];
__device__ float g_usq[NB*NN];
__device__ u32 g_maxbits;

// ---------------- warp-MMA helpers (base ISA: sm_80+) ------------------------
__device__ __forceinline__ u32 smem_u32(const void* p) {
    u32 a;
    asm("{ .reg .u64 t; cvta.to.shared.u64 t, %1; cvt.u32.u64 %0, t; }"
        : "=r"(a) : "l"(p));
    return a;
}
__device__ __forceinline__ u32 ldm_addr(u32 base, int row, int col8) {
    return base + row*128 + ((col8 ^ (row & 7)) << 4);
}
__device__ __forceinline__ void ldmx4(u32 a, u32& r0, u32& r1, u32& r2, u32& r3) {
    asm volatile("ldmatrix.sync.aligned.m8n8.x4.shared.b16 {%0,%1,%2,%3}, [%4];"
        : "=r"(r0), "=r"(r1), "=r"(r2), "=r"(r3) : "r"(a) : "memory");
}
__device__ __forceinline__ void mma16816(float* d, const u32* a, u32 b0, u32 b1) {
    asm volatile("mma.sync.aligned.m16n8k16.row.col.f32.bf16.bf16.f32 "
        "{%0,%1,%2,%3}, {%4,%5,%6,%7}, {%8,%9}, {%0,%1,%2,%3};"
        : "+f"(d[0]), "+f"(d[1]), "+f"(d[2]), "+f"(d[3])
        : "r"(a[0]), "r"(a[1]), "r"(a[2]), "r"(a[3]), "r"(b0), "r"(b1));
}
__device__ __forceinline__ void split2(float a, float b, u32& H, u32& L) {
    __nv_bfloat16 ha = __float2bfloat16(a), hb = __float2bfloat16(b);
    float ra = a - __bfloat162float(ha), rb = b - __bfloat162float(hb);
    __nv_bfloat162 hh; hh.x = ha; hh.y = hb;
    __nv_bfloat162 ll; ll.x = __float2bfloat16(ra); ll.y = __float2bfloat16(rb);
    H = *(u32*)&hh; L = *(u32*)&ll;
}

// ---------------- K0: xw = x @ W, emit transposed bf16 hi/lo directly --------
__global__ void k0_xw(const float* __restrict__ x, const float* __restrict__ W) {
    __shared__ float Wsh[FIN*FE];
    __shared__ float xsh[4][FIN];
    __shared__ float res[16][65];
    int tid = threadIdx.x;             // 256
    if (blockIdx.x == 0) {
        if (tid < NB*FE) g_cent[tid] = 0.f;
        if (tid == 128) g_maxbits = 0u;
    }
    for (int i = tid; i < FIN*FE; i += 256) Wsh[i] = W[i];
    int rowBase = blockIdx.x * 16;
    int b = rowBase >> 11, n0 = rowBase & 2047;
    int rloc = tid >> 6, e = tid & 63;
    for (int pass = 0; pass < 4; ++pass) {
        __syncthreads();
        int r0 = rowBase + pass * 4;
        for (int i = tid; i < 4*FIN; i += 256)
            xsh[i >> 7][i & 127] = x[(size_t)r0*FIN + i];
        __syncthreads();
        float acc = 0.f;
        #pragma unroll
        for (int k = 0; k < FIN; ++k)
            acc = fmaf(xsh[rloc][k], Wsh[k*FE + e], acc);
        res[pass*4 + rloc][e] = acc;
    }
    __syncthreads();
    #pragma unroll
    for (int item = tid; item < 512; item += 256) {
        int ee = item >> 3, p = item & 7;
        u32 H, L;
        split2(res[2*p][ee], res[2*p + 1][ee], H, L);
        u32 idx = (u32)(b*FE + ee) * (NN/2) + (u32)(n0 >> 1) + p;
        g_xwt_h[idx] = H;
        g_xwt_l[idx] = L;
    }
}

// ---------------- K1: partials of A @ xw, double-buffered warp-MMA -----------
// CTA 128x64, k-split 4, chunks of 64, 2-stage smem pipeline.
__global__ void __launch_bounds__(256) k1_mma(const float* __restrict__ A) {
    extern __shared__ __align__(16) char dsm[];
    int tid = threadIdx.x, wid = tid >> 5, lane = tid & 31;
    int wy = wid & 3, wx = wid >> 2;
    int sub = lane >> 3, lr = lane & 7;
    int b = blockIdx.z, ks = blockIdx.y, i0 = blockIdx.x * 128;

    u32 raw = smem_u32(dsm);
    u32 ab = (raw + 1023u) & ~1023u;
    char* AB = dsm + (ab - raw);

    const float* Ab = A + (size_t)b*NN*NN;
    int kbeg = ks * (NN/KS);

    // load-target indices (constant per thread)
    int arow = tid >> 4, akq = (tid & 15) * 4;       // + v*16 rows
    int xe = tid >> 3, xq = tid & 7;                 // v in {0,1}: e += v*32? no: idx=tid+v*256 -> e=idx>>3
    float4 aR[8];
    uint4 xhR[2], xlR[2];

    #define K1_LD(k0_) do {                                                    \
        _Pragma("unroll")                                                      \
        for (int v = 0; v < 8; ++v)                                            \
            aR[v] = *(const float4*)(Ab + (size_t)(i0 + arow + v*16)*NN + (k0_) + akq); \
        _Pragma("unroll")                                                      \
        for (int v = 0; v < 2; ++v) {                                          \
            int e_ = xe + v*32;                                                \
            u32 srci = (u32)(b*FE + e_) * (NN/2) + (u32)((k0_) >> 1);          \
            xhR[v] = *((const uint4*)(g_xwt_h + srci) + xq);                   \
            xlR[v] = *((const uint4*)(g_xwt_l + srci) + xq);                   \
        }                                                                      \
    } while (0)

    #define K1_ST(S_) do {                                                     \
        char* AH_ = (S_); char* AL_ = (S_) + 16384;                            \
        char* XH_ = (S_) + 32768; char* XL_ = (S_) + 40960;                    \
        _Pragma("unroll")                                                      \
        for (int v = 0; v < 8; ++v) {                                          \
            int row = arow + v*16;                                             \
            u32 h01, l01, h23, l23;                                            \
            split2(aR[v].x, aR[v].y, h01, l01);                                \
            split2(aR[v].z, aR[v].w, h23, l23);                                \
            int off = row*128 + akq*2; off ^= (off >> 3) & 0x70;               \
            *(u64*)(AH_ + off) = (u64)h01 | ((u64)h23 << 32);                  \
            *(u64*)(AL_ + off) = (u64)l01 | ((u64)l23 << 32);                  \
        }                                                                      \
        _Pragma("unroll")                                                      \
        for (int v = 0; v < 2; ++v) {                                          \
            int e_ = xe + v*32;                                                \
            int off = e_*128 + xq*16; off ^= (off >> 3) & 0x70;                \
            *(uint4*)(XH_ + off) = xhR[v];                                     \
            *(uint4*)(XL_ + off) = xlR[v];                                     \
        }                                                                      \
    } while (0)

    float acc[2][4][4];
    #pragma unroll
    for (int m = 0; m < 2; ++m)
        #pragma unroll
        for (int n = 0; n < 4; ++n)
            #pragma unroll
            for (int q = 0; q < 4; ++q) acc[m][n][q] = 0.f;

    K1_LD(kbeg);
    K1_ST(AB);
    __syncthreads();

    for (int it = 0; it < 8; ++it) {
        if (it < 7) K1_LD(kbeg + (it + 1) * 64);
        u32 sb = ab + (u32)(it & 1) * 49152;
        u32 abH = sb, abL = sb + 16384, xbH = sb + 32768, xbL = sb + 40960;
        #pragma unroll
        for (int kp = 0; kp < 4; ++kp) {
            int c8 = kp * 2;
            u32 aH[2][4], aL[2][4];
            #pragma unroll
            for (int mt = 0; mt < 2; ++mt) {
                int r = wy*32 + mt*16 + lr + (sub & 1)*8;
                int cc = c8 + (sub >> 1);
                ldmx4(ldm_addr(abH, r, cc), aH[mt][0], aH[mt][1], aH[mt][2], aH[mt][3]);
                ldmx4(ldm_addr(abL, r, cc), aL[mt][0], aL[mt][1], aL[mt][2], aL[mt][3]);
            }
            #pragma unroll
            for (int np = 0; np < 2; ++np) {
                int rb = wx*32 + np*16 + lr + (sub >> 1)*8;
                int cb = c8 + (sub & 1);
                u32 bh[4], bl[4];
                ldmx4(ldm_addr(xbH, rb, cb), bh[0], bh[1], bh[2], bh[3]);
                ldmx4(ldm_addr(xbL, rb, cb), bl[0], bl[1], bl[2], bl[3]);
                #pragma unroll
                for (int mt = 0; mt < 2; ++mt)
                    #pragma unroll
                    for (int t = 0; t < 2; ++t) {
                        float* d = acc[mt][np*2 + t];
                        mma16816(d, aH[mt], bh[2*t], bh[2*t+1]);
                        mma16816(d, aH[mt], bl[2*t], bl[2*t+1]);
                        mma16816(d, aL[mt], bh[2*t], bh[2*t+1]);
                    }
            }
        }
        if (it < 7) {
            K1_ST(AB + ((it + 1) & 1) * 49152);
            __syncthreads();
        }
    }
    float* P = g_part + (size_t)ks*SLICE + (size_t)b*NN*FE;
    #pragma unroll
    for (int mt = 0; mt < 2; ++mt) {
        int gi = i0 + wy*32 + mt*16 + (lane >> 2);
        #pragma unroll
        for (int nt = 0; nt < 4; ++nt) {
            int c = wx*32 + nt*8 + 2*(lane & 3);
            float* d = acc[mt][nt];
            *(float2*)(P + (size_t)gi*FE + c)       = make_float2(d[0], d[1]);
            *(float2*)(P + (size_t)(gi + 8)*FE + c) = make_float2(d[2], d[3]);
        }
    }
}

// ---------------- K1b: x_emb = relu(sum partials + bias), + centroid ---------
__global__ void k1b_bias(const float* __restrict__ bias, float* __restrict__ out) {
    int tid = threadIdx.x;                     // 1024
    int i4 = blockIdx.x * 1024 + tid;          // 64 blocks, 4 floats/thread
    size_t i = (size_t)i4 * 4;
    int e0 = (int)(i & 63);
    float4 v = make_float4(bias[e0], bias[e0+1], bias[e0+2], bias[e0+3]);
    #pragma unroll
    for (int s = 0; s < KS; ++s) {
        float4 p = *(const float4*)(g_part + (size_t)s*SLICE + i);
        v.x += p.x; v.y += p.y; v.z += p.z; v.w += p.w;
    }
    v.x = fmaxf(v.x, 0.f); v.y = fmaxf(v.y, 0.f);
    v.z = fmaxf(v.z, 0.f); v.w = fmaxf(v.w, 0.f);
    *(float4*)(out + i) = v;
    __shared__ float cs[64];
    if (tid < 64) cs[tid] = 0.f;
    __syncthreads();
    // lanes l and l+16 hit the same e-quad -> pair-reduce, half the atomics
    v.x += __shfl_down_sync(0xffffffffu, v.x, 16);
    v.y += __shfl_down_sync(0xffffffffu, v.y, 16);
    v.z += __shfl_down_sync(0xffffffffu, v.z, 16);
    v.w += __shfl_down_sync(0xffffffffu, v.w, 16);
    if ((tid & 31) < 16) {
        atomicAdd(&cs[e0],   v.x);
        atomicAdd(&cs[e0+1], v.y);
        atomicAdd(&cs[e0+2], v.z);
        atomicAdd(&cs[e0+3], v.w);
    }
    __syncthreads();
    if (tid < 64) {
        int b = blockIdx.x >> 5;               // 64 rows/block, 32 blocks/batch
        atomicAdd(&g_cent[b*FE + tid], cs[tid] * (1.f/NN));
    }
}

// ---------------- K3: usq + max|x-c| + centered bf16 split -------------------
__global__ void k3_usq(const float* __restrict__ xemb) {
    int tid = threadIdx.x, w = tid >> 5, l = tid & 31;
    int row = blockIdx.x * 8 + w;      // grid 512
    int b = row >> 11;
    float2 t = *(const float2*)(xemb + (size_t)row*FE + 2*l);
    float2 c = *(const float2*)(g_cent + b*FE + 2*l);
    float v0 = t.x - c.x, v1 = t.y - c.y;
    u32 H, L;
    split2(v0, v1, H, L);
    g_csh[row*32 + l] = H;
    g_csl[row*32 + l] = L;
    float sq = v0*v0 + v1*v1;
    float av = fmaxf(fabsf(v0), fabsf(v1));
    #pragma unroll
    for (int o = 16; o; o >>= 1) {
        sq += __shfl_xor_sync(0xffffffffu, sq, o);
        av = fmaxf(av, __shfl_xor_sync(0xffffffffu, av, o));
    }
    if (l == 0) g_usq[row] = sq;
    __shared__ float wm[8];
    if (l == 0) wm[w] = av;
    __syncthreads();
    if (tid == 0) {
        float m = wm[0];
        #pragma unroll
        for (int i = 1; i < 8; ++i) m = fmaxf(m, wm[i]);
        atomicMax(&g_maxbits, __float_as_uint(m));
    }
}

__device__ __forceinline__ float sigw(float a, float ui, float uj,
                                      float s2, float T, float TH) {
    float dd = fmaxf(s2 * (ui + uj - 2.f*a), 0.f);
    float z = T * (TH - dd);
    return __fdividef(1.f, 1.f + __expf(-z));
}

// ---------------- K5: Gram via warp-MMA + distances + sigmoid + edge_index ---
__global__ void __launch_bounds__(256) k5_mma(const float* __restrict__ temp,
                                              const float* __restrict__ thr,
                                              float* __restrict__ out) {
    extern __shared__ __align__(16) char dsm[];
    __shared__ float usqi[128], usqj[128];
    int tid = threadIdx.x, wid = tid >> 5, lane = tid & 31;
    int wy = wid & 3, wx = wid >> 2;
    int sub = lane >> 3, lr = lane & 7;
    int b = blockIdx.z, i0 = blockIdx.y * 128, j0 = blockIdx.x * 128;

    u32 raw = smem_u32(dsm);
    u32 ab = (raw + 1023u) & ~1023u;
    char* AB = dsm + (ab - raw);
    u32 tiH = ab, tiL = ab + 16384, tjH = ab + 32768, tjL = ab + 49152;

    #pragma unroll
    for (int t = 0; t < 4; ++t) {
        int rb = (t < 2) ? i0 : j0;
        const u32* src = (t & 1) ? g_csl : g_csh;
        char* dst = AB + t*16384;
        #pragma unroll
        for (int v = 0; v < 4; ++v) {
            int idx = tid + v*256;
            int row = idx >> 3, q = idx & 7;
            uint4 val = *((const uint4*)(src + ((size_t)(b*NN + rb + row) << 5)) + q);
            int off = row*128 + q*16; off ^= (off >> 3) & 0x70;
            *(uint4*)(dst + off) = val;
        }
    }
    if (tid < 128) usqi[tid] = g_usq[b*NN + i0 + tid];
    else           usqj[tid-128] = g_usq[b*NN + j0 + (tid-128)];
    __syncthreads();

    float acc[2][8][4];
    #pragma unroll
    for (int m = 0; m < 2; ++m)
        #pragma unroll
        for (int n = 0; n < 8; ++n)
            #pragma unroll
            for (int q = 0; q < 4; ++q) acc[m][n][q] = 0.f;

    #pragma unroll
    for (int kp = 0; kp < 4; ++kp) {
        int c8 = kp * 2;
        u32 aH[2][4], aL[2][4];
        #pragma unroll
        for (int mt = 0; mt < 2; ++mt) {
            int r = wy*32 + mt*16 + lr + (sub & 1)*8;
            int cc = c8 + (sub >> 1);
            ldmx4(ldm_addr(tiH, r, cc), aH[mt][0], aH[mt][1], aH[mt][2], aH[mt][3]);
            ldmx4(ldm_addr(tiL, r, cc), aL[mt][0], aL[mt][1], aL[mt][2], aL[mt][3]);
        }
        #pragma unroll
        for (int np = 0; np < 4; ++np) {
            int rb = wx*64 + np*16 + lr + (sub >> 1)*8;
            int cb = c8 + (sub & 1);
            u32 bh[4], bl[4];
            ldmx4(ldm_addr(tjH, rb, cb), bh[0], bh[1], bh[2], bh[3]);
            ldmx4(ldm_addr(tjL, rb, cb), bl[0], bl[1], bl[2], bl[3]);
            #pragma unroll
            for (int mt = 0; mt < 2; ++mt)
                #pragma unroll
                for (int t = 0; t < 2; ++t) {
                    float* d = acc[mt][np*2 + t];
                    mma16816(d, aH[mt], bh[2*t], bh[2*t+1]);
                    mma16816(d, aH[mt], bl[2*t], bl[2*t+1]);
                    mma16816(d, aL[mt], bh[2*t], bh[2*t+1]);
                }
        }
    }

    float s = 0.9f / __uint_as_float(g_maxbits);
    float s2 = s * s;
    float T = *temp, TH = fabsf(*thr);
    float* WgB = out + OFF_WGT + (size_t)b*NN*NN;
    float* RoB = out + OFF_ROWS;
    float* CoB = out + OFF_ROWS + BN2;
    #pragma unroll
    for (int mt = 0; mt < 2; ++mt) {
        int li = wy*32 + mt*16 + (lane >> 2);
        int gi0 = i0 + li, gi8 = gi0 + 8;
        float ui0 = usqi[li], ui8 = usqi[li + 8];
        float rv0 = (float)(b*NN + gi0), rv8 = (float)(b*NN + gi8);
        size_t w0 = (size_t)gi0*NN + j0, w8 = (size_t)gi8*NN + j0;
        size_t e0 = ((size_t)b*NN + gi0)*NN + j0, e8 = ((size_t)b*NN + gi8)*NN + j0;
        #pragma unroll
        for (int nt = 0; nt < 8; ++nt) {
            int c = wx*64 + nt*8 + 2*(lane & 3);
            float uj0 = usqj[c], uj1 = usqj[c + 1];
            float* d = acc[mt][nt];
            float cj = (float)(j0 + c + NN*b);
            *(float2*)(WgB + w0 + c) = make_float2(sigw(d[0], ui0, uj0, s2, T, TH),
                                                   sigw(d[1], ui0, uj1, s2, T, TH));
            *(float2*)(WgB + w8 + c) = make_float2(sigw(d[2], ui8, uj0, s2, T, TH),
                                                   sigw(d[3], ui8, uj1, s2, T, TH));
            *(float2*)(RoB + e0 + c) = make_float2(rv0, rv0);
            *(float2*)(RoB + e8 + c) = make_float2(rv8, rv8);
            *(float2*)(CoB + e0 + c) = make_float2(cj, cj + 1.f);
            *(float2*)(CoB + e8 + c) = make_float2(cj, cj + 1.f);
        }
    }
}

extern "C" void kernel_launch(void* const* d_in, const int* in_sizes, int n_in,
                              void* d_out, int out_size) {
    const float* x    = (const float*)d_in[0];
    const float* A    = (const float*)d_in[1];
    const float* W    = (const float*)d_in[2];
    const float* bias = (const float*)d_in[3];
    const float* temp = (const float*)d_in[4];
    const float* thr  = (const float*)d_in[5];
    float* out = (float*)d_out;

    cudaFuncSetAttribute(k1_mma, cudaFuncAttributeMaxDynamicSharedMemorySize, 99328);
    cudaFuncSetAttribute(k5_mma, cudaFuncAttributeMaxDynamicSharedMemorySize, 66560);

    k0_xw<<<NB*NN/16, 256>>>(x, W);
    k1_mma<<<dim3(NN/128, KS, NB), 256, 99328>>>(A);
    k1b_bias<<<(NB*NN*FE)/4096, 1024>>>(bias, out);
    k3_usq<<<NB*NN/8, 256>>>(out);
    k5_mma<<<dim3(NN/128, NN/128, NB), 256, 66560>>>(temp, thr, out);
}